// round 10
// baseline (speedup 1.0000x reference)
#include <cuda_runtime.h>
#include <math.h>

// ---------------------------------------------------------------------------
// expression[c,g] = bias1[gene_ix[g]] + sum_{frags in bucket c*gene_n+g}
//                   dot(sin(coords[f,:,None]*freq+shift).reshape(40), w)
// Per-fragment scalar g0(x)+g1(y): two fixed 1-D LUTs + lerp (err ~3e-6).
// R10 = R5 + flush-op downgrade: buckets interior to a 128-frag window have
// exactly ONE writer grid-wide -> plain STG of bias+total; only the window's
// first/last-run buckets (possible cross-window sharing) keep global RED.
// ---------------------------------------------------------------------------

#define TAB      256
#define T_LO     (-9.0f)
#define T_HI     ( 9.0f)
#define FULL     0xffffffffu
#define MAX_GENE 2048

__device__ float2 g_tbl[2][TAB];     // (value, slope-to-next)

// ---------------------------------------------------------------------------
// prep: first TBL_BLOCKS blocks build the LUT; remaining init out = bias.
// ---------------------------------------------------------------------------
#define TBL_POINTS  (2 * TAB)
#define TBL_BLOCKS  ((TBL_POINTS * 32 + 255) / 256)
#define INIT_ROWS   8

__global__ void prep_kernel(const float* __restrict__ freqs,
                            const float* __restrict__ shifts,
                            const float* __restrict__ w,
                            const float* __restrict__ bias,
                            const int*   __restrict__ gene_ix,
                            float*       __restrict__ out,
                            int gene_n, int total)
{
    if (blockIdx.x < TBL_BLOCKS) {
        int gw   = blockIdx.x * (blockDim.x >> 5) + (threadIdx.x >> 5);
        int lane = threadIdx.x & 31;
        if (gw < TBL_POINTS) {
            int which = gw / TAB;
            int k     = gw % TAB;
            const float step = (T_HI - T_LO) / (float)TAB;
            float x0 = T_LO + (float)k * step;
            float x1 = x0 + step;
            float v0 = 0.f, v1 = 0.f;
            if (lane < 20) {
                float f = freqs[lane], s = shifts[lane], c = w[which * 20 + lane];
                v0 = c * sinf(fmaf(x0, f, s));
                v1 = c * sinf(fmaf(x1, f, s));
            }
            #pragma unroll
            for (int off = 16; off; off >>= 1) {
                v0 += __shfl_down_sync(FULL, v0, off);
                v1 += __shfl_down_sync(FULL, v1, off);
            }
            if (lane == 0) g_tbl[which][k] = make_float2(v0, v1 - v0);
        }
        return;
    }

    int ib = blockIdx.x - TBL_BLOCKS;

    if ((gene_n & 3) == 0 && gene_n <= 4096 && total % gene_n == 0) {
        __shared__ float pb[4096];
        for (int g = threadIdx.x; g < gene_n; g += blockDim.x)
            pb[g] = __ldg(&bias[__ldg(&gene_ix[g])]);
        __syncthreads();

        const float4* pb4 = reinterpret_cast<const float4*>(pb);
        float4*       o4  = reinterpret_cast<float4*>(out);
        int row_q  = gene_n >> 2;
        int rows   = total / gene_n;
        int r0     = ib * INIT_ROWS;
        int nq     = min(INIT_ROWS, rows - r0) * row_q;
        if (nq <= 0) return;
        long base4 = (long)r0 * row_q;
        for (int t = threadIdx.x; t < nq; t += blockDim.x)
            o4[base4 + t] = pb4[t % row_q];
    } else {
        for (long i = (long)ib * blockDim.x * INIT_ROWS * 4 + threadIdx.x;
             i < (long)total && i < (long)(ib + 1) * blockDim.x * INIT_ROWS * 4;
             i += blockDim.x)
            out[i] = __ldg(&bias[__ldg(&gene_ix[(int)(i % gene_n)])]);
    }
}

// ---------------------------------------------------------------------------
__device__ __forceinline__ float lerp1(const float2* __restrict__ s, float x)
{
    const float scale = (float)TAB / (T_HI - T_LO);
    const float offs  = -T_LO * scale;
    const float hi    = (float)TAB - 0.001f;
    float u = fminf(fmaxf(fmaf(x, scale, offs), 0.f), hi);
    int   k = (int)u;
    float fr = u - (float)k;
    float2 t = s[k];
    return fmaf(fr, t.y, t.x);
}

// One flush: interior bucket -> STG(bias+v); window-boundary bucket -> RED(v).
__device__ __forceinline__ void flush_sg(float* __restrict__ out,
                                         const float* __restrict__ bias_sm,
                                         bool pred, bool stg_ok,
                                         int b, float v,
                                         int b_first, int b_last,
                                         float inv_g, int g)
{
    bool boundary = (b == b_first) || (b == b_last) || !stg_ok;
    bool do_stg = pred && !boundary;
    bool do_red = pred && boundary;

    // exact b % g for 0 <= b < 2^24 (float mul + correction)
    int q = (int)((float)b * inv_g);
    int m = b - q * g;
    m = (m < 0)  ? m + g : m;
    m = (m >= g) ? m - g : m;

    float sv = 0.f;
    if (do_stg) sv = bias_sm[m] + v;   // predicated LDS (safe index only when pred)
    if (do_stg) out[b] = sv;
    if (do_red) atomicAdd(out + b, v);
}

__global__ void __launch_bounds__(256)
frag_kernel(const float4* __restrict__ coords2,   // 2 frags per element
            const int4*   __restrict__ ix4,       // 4 bucket ids per element
            const float*  __restrict__ coords_raw,
            const int*    __restrict__ ix_raw,
            const float*  __restrict__ bias,
            const int*    __restrict__ gene_ix,
            float*        __restrict__ out,
            int nquads, int F, int gene_n, float inv_g)
{
    __shared__ float2 s0[TAB];
    __shared__ float2 s1[TAB];
    __shared__ float  bias_sm[MAX_GENE];
    {
        const float2* src = &g_tbl[0][0];
        for (int i = threadIdx.x; i < 2 * TAB; i += blockDim.x) {
            float2 v = src[i];
            if (i < TAB) s0[i] = v; else s1[i - TAB] = v;
        }
    }
    bool stg_ok = (gene_n <= MAX_GENE);
    if (stg_ok)
        for (int g = threadIdx.x; g < gene_n; g += blockDim.x)
            bias_sm[g] = __ldg(&bias[__ldg(&gene_ix[g])]);
    __syncthreads();

    // Leftover fragments (F % 4): one thread, always RED.
    if (blockIdx.x == 0 && threadIdx.x == 0) {
        for (int f = 4 * nquads; f < F; ++f) {
            float x = coords_raw[2 * f], y = coords_raw[2 * f + 1];
            atomicAdd(out + ix_raw[f], lerp1(s0, x) + lerp1(s1, y));
        }
    }

    int lane   = threadIdx.x & 31;
    int gwarp  = (blockIdx.x * blockDim.x + threadIdx.x) >> 5;
    int nwarps = (gridDim.x * blockDim.x) >> 5;

    for (long qbase = (long)gwarp * 32; qbase < (long)nquads;
         qbase += (long)nwarps * 32) {
        long q     = qbase + lane;
        bool valid = q < (long)nquads;

        float4 cA = make_float4(0,0,0,0), cB = make_float4(0,0,0,0);
        int4   bb = make_int4(-1,-1,-1,-1);
        if (valid) {
            cA = __ldcs(&coords2[2 * q]);
            cB = __ldcs(&coords2[2 * q + 1]);
            bb = __ldcs(&ix4[q]);
        }

        float v0 = lerp1(s0, cA.x) + lerp1(s1, cA.y);
        float v1 = lerp1(s0, cA.z) + lerp1(s1, cA.w);
        float v2 = lerp1(s0, cB.x) + lerp1(s1, cB.y);
        float v3 = lerp1(s0, cB.z) + lerp1(s1, cB.w);

        // Branchless cumulative run sums over the 4 sorted buckets.
        bool e01 = (bb.x == bb.y), e12 = (bb.y == bb.z), e23 = (bb.z == bb.w);
        float c0 = v0;
        float c1 = v1 + (e01 ? c0 : 0.f);
        float c2 = v2 + (e12 ? c1 : 0.f);
        float c3 = v3 + (e23 ? c2 : 0.f);
        bool  same = e01 && e12 && e23;
        float hsum = !e01 ? c0 : (!e12 ? c1 : c2);

        // Window first/last buckets (possible cross-window sharers).
        int b_first = __shfl_sync(FULL, bb.x, 0);
        unsigned vm = __ballot_sync(FULL, valid);
        int hl      = 31 - __clz(vm);                // lane 0 always valid
        int b_last  = __shfl_sync(FULL, bb.w, hl);

        // Tail run (bucket bb.w, sum c3) feeds the cross-lane segmented scan.
        int  st_prev = __shfl_up_sync(FULL, bb.w, 1);
        bool cont    = (lane > 0) && same && (st_prev == bb.w);

        unsigned hb    = __ballot_sync(FULL, !cont);
        unsigned below = hb & (0xffffffffu >> (31 - lane));
        int seg = 31 - __clz(below);                 // bit 0 always set

        float S = c3;
        #pragma unroll
        for (int off = 1; off < 32; off <<= 1) {
            float n = __shfl_up_sync(FULL, S, off);
            if (lane - off >= seg) S += n;
        }

        float Sprev = __shfl_up_sync(FULL, S, 1);
        int   nb0   = __shfl_down_sync(FULL, bb.x, 1);
        bool consumed = (lane < 31) && (nb0 == bb.w);

        bool f_int1 = valid && !e12 && !e01;
        bool f_int2 = valid && !e23 && !(e01 && e12);
        bool f_head = valid && !same;
        bool f_tail = valid && !consumed;
        float hv = hsum + ((lane > 0 && st_prev == bb.x) ? Sprev : 0.f);

        flush_sg(out, bias_sm, f_int1, stg_ok, bb.y, c1, b_first, b_last, inv_g, gene_n);
        flush_sg(out, bias_sm, f_int2, stg_ok, bb.z, c2, b_first, b_last, inv_g, gene_n);
        flush_sg(out, bias_sm, f_head, stg_ok, bb.x, hv, b_first, b_last, inv_g, gene_n);
        flush_sg(out, bias_sm, f_tail, stg_ok, bb.w, S,  b_first, b_last, inv_g, gene_n);
    }
}

// ---------------------------------------------------------------------------
extern "C" void kernel_launch(void* const* d_in, const int* in_sizes, int n_in,
                              void* d_out, int out_size)
{
    // 0 coords, 1 cellxgene_ix, 2 cell_n, 3 gene_n, 4 gene_ix,
    // 5 frequencies, 6 shifts, 7 weight1, 8 bias1
    int off = (n_in >= 9) ? 0 : -2;

    const float* coords  = (const float*)d_in[0];
    const int*   ix      = (const int*)  d_in[1];
    const int*   gene_ix = (const int*)  d_in[4 + off];
    const float* freqs   = (const float*)d_in[5 + off];
    const float* shifts  = (const float*)d_in[6 + off];
    const float* w       = (const float*)d_in[7 + off];
    const float* bias    = (const float*)d_in[8 + off];

    int F      = in_sizes[0] / 2;
    int gene_n = in_sizes[4 + off];
    float* out = (float*)d_out;

    int init_blocks;
    if ((gene_n & 3) == 0 && gene_n <= 4096 && out_size % gene_n == 0) {
        int rows = out_size / gene_n;
        init_blocks = (rows + INIT_ROWS - 1) / INIT_ROWS;
    } else {
        init_blocks = (out_size + 256 * INIT_ROWS * 4 - 1) / (256 * INIT_ROWS * 4);
    }
    prep_kernel<<<TBL_BLOCKS + init_blocks, 256>>>(freqs, shifts, w, bias,
                                                   gene_ix, out, gene_n, out_size);

    int nquads = F / 4;
    frag_kernel<<<1184, 256>>>((const float4*)coords, (const int4*)ix,
                               coords, ix, bias, gene_ix, out,
                               nquads, F, gene_n, 1.0f / (float)gene_n);
}